// round 6
// baseline (speedup 1.0000x reference)
#include <cuda_runtime.h>
#include <cuda_bf16.h>
#include <cstdint>

#define DIM 64
#define NCI_MAX 150000
#define FMA_MAX 100000
#define GATHER_BLOCKS 1184          // 148 SMs x 8 resident blocks = one full wave
#define GATHER_TPB 256
#define CONV_BLOCKS 512

// ---------------- scratch (device globals: allocation-free rule) ----------------
__device__ __align__(128) __nv_bfloat16 g_Hn[NCI_MAX * DIM];   // 19.2 MB
__device__ __align__(128) __nv_bfloat16 g_Hm[NCI_MAX * DIM];   // 19.2 MB
__device__ __align__(128) __nv_bfloat16 g_Fb[FMA_MAX * DIM];   // 12.8 MB
__device__ float g_part[GATHER_BLOCKS];
__device__ unsigned g_ticket;

// ---------------- HMMA: m16n8k16 bf16 -> f32 ----------------
__device__ __forceinline__ void mma16816(float* d, const uint32_t* a, const uint32_t* b) {
    asm volatile(
        "mma.sync.aligned.m16n8k16.row.col.f32.bf16.bf16.f32 "
        "{%0,%1,%2,%3}, {%4,%5,%6,%7}, {%8,%9}, {%0,%1,%2,%3};"
        : "+f"(d[0]), "+f"(d[1]), "+f"(d[2]), "+f"(d[3])
        : "r"(a[0]), "r"(a[1]), "r"(a[2]), "r"(a[3]), "r"(b[0]), "r"(b[1]));
}

#define SROW 72   // padded bf16 row stride -> conflict-free fragment loads

// ---------------- packed f32x2 helpers ----------------
__device__ __forceinline__ unsigned long long ffma2(unsigned long long a,
                                                    unsigned long long b,
                                                    unsigned long long c) {
    unsigned long long d;
    asm("fma.rn.f32x2 %0, %1, %2, %3;" : "=l"(d) : "l"(a), "l"(b), "l"(c));
    return d;
}
__device__ __forceinline__ unsigned long long fadd2(unsigned long long a,
                                                    unsigned long long b) {
    unsigned long long d;
    asm("add.rn.f32x2 %0, %1, %2;" : "=l"(d) : "l"(a), "l"(b));
    return d;
}
__device__ __forceinline__ void unpack2(unsigned long long v, float& lo, float& hi) {
    asm("mov.b64 {%0, %1}, %2;" : "=f"(lo), "=f"(hi) : "l"(v));
}
// bf16 pair -> packed f32x2 (exact: bf16 == top half of f32)
__device__ __forceinline__ unsigned long long b2f2(unsigned u) {
    unsigned lo = u << 16;
    unsigned hi = u & 0xffff0000u;
    unsigned long long r;
    asm("mov.b64 %0, {%1, %2};" : "=l"(r) : "r"(lo), "r"(hi));
    return r;
}
// (h - f) in bf16x2, then square-accumulate in packed f32
__device__ __forceinline__ void sqacc(unsigned hu, unsigned fu,
                                      unsigned long long& acc) {
    __nv_bfloat162 h2 = *reinterpret_cast<__nv_bfloat162*>(&hu);
    __nv_bfloat162 f2 = *reinterpret_cast<__nv_bfloat162*>(&fu);
    __nv_bfloat162 d2 = __hsub2(h2, f2);
    unsigned du = *reinterpret_cast<unsigned*>(&d2);
    unsigned long long d = b2f2(du);
    acc = ffma2(d, d, acc);
}

// ---------------- kernel 1: HMMA precompute + F convert (fused grid) ----------------
__global__ __launch_bounds__(256) void prep_mma(
    const float* __restrict__ nci,
    const float* __restrict__ Mn,
    const float* __restrict__ Mm,
    const float* __restrict__ fmae,
    int nrows, int hBlocks, int f_elems)
{
    const int tid = threadIdx.x;

    if (blockIdx.x >= hBlocks) {
        int cb = blockIdx.x - hBlocks;
        int stride = CONV_BLOCKS * 256;
        int nv = f_elems >> 2;
        for (int k = cb * 256 + tid; k < nv; k += stride) {
            float4 v = reinterpret_cast<const float4*>(fmae)[k];
            __nv_bfloat162* o = reinterpret_cast<__nv_bfloat162*>(g_Fb) + (size_t)k * 2;
            o[0] = __floats2bfloat162_rn(v.x, v.y);
            o[1] = __floats2bfloat162_rn(v.z, v.w);
        }
        return;
    }

    __shared__ __align__(16) __nv_bfloat16 sA[128][SROW];
    __shared__ __align__(16) __nv_bfloat16 sB[128][SROW];

    const int lane = tid & 31;
    const int w    = tid >> 5;
    const int gr   = lane >> 2;
    const int c    = lane & 3;
    const int rowBase = blockIdx.x * 128;

#pragma unroll
    for (int it = 0; it < 8; it++) {
        int idx = it * 256 + tid;
        int r = idx >> 4;
        int cq = idx & 15;
        int grow = rowBase + r;
        float4 v = (grow < nrows)
            ? reinterpret_cast<const float4*>(nci)[(size_t)grow * 16 + cq]
            : make_float4(0.f, 0.f, 0.f, 0.f);
        __nv_bfloat162 p0 = __floats2bfloat162_rn(v.x, v.y);
        __nv_bfloat162 p1 = __floats2bfloat162_rn(v.z, v.w);
        uint2 pk = make_uint2(*reinterpret_cast<uint32_t*>(&p0),
                              *reinterpret_cast<uint32_t*>(&p1));
        *reinterpret_cast<uint2*>(&sA[r][cq * 4]) = pk;
    }
#pragma unroll
    for (int it = 0; it < 8; it++) {
        int idx = it * 256 + tid;
        int r = idx >> 4;
        int cq = idx & 15;
        const float4* src = reinterpret_cast<const float4*>(r < 64 ? Mn : Mm);
        float4 v = src[(size_t)(r & 63) * 16 + cq];
        __nv_bfloat162 p0 = __floats2bfloat162_rn(v.x, v.y);
        __nv_bfloat162 p1 = __floats2bfloat162_rn(v.z, v.w);
        uint2 pk = make_uint2(*reinterpret_cast<uint32_t*>(&p0),
                              *reinterpret_cast<uint32_t*>(&p1));
        *reinterpret_cast<uint2*>(&sB[r][cq * 4]) = pk;
    }
    __syncthreads();

    float acc[16][4];
#pragma unroll
    for (int t = 0; t < 16; t++)
#pragma unroll
        for (int q = 0; q < 4; q++) acc[t][q] = 0.f;

#pragma unroll
    for (int kk = 0; kk < 4; kk++) {
        uint32_t a[4];
        const int ar0 = w * 16 + gr;
        const int ak  = kk * 16 + 2 * c;
        a[0] = *reinterpret_cast<const uint32_t*>(&sA[ar0][ak]);
        a[1] = *reinterpret_cast<const uint32_t*>(&sA[ar0 + 8][ak]);
        a[2] = *reinterpret_cast<const uint32_t*>(&sA[ar0][ak + 8]);
        a[3] = *reinterpret_cast<const uint32_t*>(&sA[ar0 + 8][ak + 8]);
#pragma unroll
        for (int t = 0; t < 16; t++) {
            uint32_t b[2];
            const int bn = t * 8 + gr;
            b[0] = *reinterpret_cast<const uint32_t*>(&sB[bn][ak]);
            b[1] = *reinterpret_cast<const uint32_t*>(&sB[bn][ak + 8]);
            mma16816(acc[t], a, b);
        }
    }

    const int r0 = rowBase + w * 16 + gr;
    const int r1 = r0 + 8;
#pragma unroll
    for (int t = 0; t < 16; t++) {
        int col = t * 8 + 2 * c;
        __nv_bfloat16* tab = (col < 64) ? g_Hn : g_Hm;
        int cc = col & 63;
        __nv_bfloat162 v0 = __floats2bfloat162_rn(acc[t][0], acc[t][1]);
        __nv_bfloat162 v1 = __floats2bfloat162_rn(acc[t][2], acc[t][3]);
        if (r0 < nrows)
            *reinterpret_cast<__nv_bfloat162*>(tab + (size_t)r0 * 64 + cc) = v0;
        if (r1 < nrows)
            *reinterpret_cast<__nv_bfloat162*>(tab + (size_t)r1 * 64 + cc) = v1;
    }
}

// ---------------- kernel 2: 8-lane-cooperative gather + fused reduce ----------------
// 8 lanes share one sample's 128B row; each warp-LDG.128 serves 4 samples / 4 lines.
// B is a multiple of 32, so every warp-step is full: no tail guards.
__global__ __launch_bounds__(GATHER_TPB, 8) void gather_loss(
    const int* __restrict__ pos_n,
    const int* __restrict__ pos_m,
    const int* __restrict__ pos_f,
    int B, float* __restrict__ out)
{
    const int lane = threadIdx.x & 31;
    const int wloc = threadIdx.x >> 5;
    const int warp = blockIdx.x * (GATHER_TPB >> 5) + wloc;
    const int nwarp = GATHER_BLOCKS * (GATHER_TPB >> 5);
    const int grp = lane >> 3;          // sample-group 0..3 within warp-step
    const int sub = lane & 7;           // 16B chunk within 128B row

    const char* baseHn = reinterpret_cast<const char*>(g_Hn) + sub * 16;
    const char* baseHm = reinterpret_cast<const char*>(g_Hm) + sub * 16;
    const char* baseFb = reinterpret_cast<const char*>(g_Fb) + sub * 16;

    unsigned long long accN = 0ull, accM = 0ull;

    for (int base = warp * 32; base < B; base += nwarp * 32) {
        const int i = base + lane;
        const int vn = pos_n[i];
        const int vm = pos_m[i];
        const int vf = pos_f[i];
#pragma unroll
        for (int t = 0; t < 8; t++) {
            const int s = t * 4 + grp;
            int an = __shfl_sync(0xffffffffu, vn, s);
            int am = __shfl_sync(0xffffffffu, vm, s);
            int af = __shfl_sync(0xffffffffu, vf, s);
            uint4 a = *reinterpret_cast<const uint4*>(baseHn + an * 128);
            uint4 b = *reinterpret_cast<const uint4*>(baseHm + am * 128);
            uint4 f = *reinterpret_cast<const uint4*>(baseFb + af * 128);
            sqacc(a.x, f.x, accN);
            sqacc(a.y, f.y, accN);
            sqacc(a.z, f.z, accN);
            sqacc(a.w, f.w, accN);
            sqacc(b.x, f.x, accM);
            sqacc(b.y, f.y, accM);
            sqacc(b.z, f.z, accM);
            sqacc(b.w, f.w, accM);
        }
    }

    unsigned long long accT = fadd2(accN, accM);
    float a0, a1;
    unpack2(accT, a0, a1);
    float acc = a0 + a1;

#pragma unroll
    for (int off = 16; off > 0; off >>= 1)
        acc += __shfl_xor_sync(0xffffffffu, acc, off);

    __shared__ float ws[GATHER_TPB / 32];
    __shared__ bool isLast;
    if (lane == 0) ws[wloc] = acc;
    __syncthreads();
    if (threadIdx.x == 0) {
        float v = 0.f;
#pragma unroll
        for (int k = 0; k < GATHER_TPB / 32; k++) v += ws[k];
        g_part[blockIdx.x] = v;
        __threadfence();
        unsigned prev = atomicInc(&g_ticket, GATHER_BLOCKS - 1);
        isLast = (prev == GATHER_BLOCKS - 1);
    }
    __syncthreads();

    if (isLast) {
        float a = 0.0f;
        for (int i = threadIdx.x; i < GATHER_BLOCKS; i += GATHER_TPB)
            a += g_part[i];
#pragma unroll
        for (int off = 16; off > 0; off >>= 1)
            a += __shfl_xor_sync(0xffffffffu, a, off);
        if (lane == 0) ws[wloc] = a;
        __syncthreads();
        if (threadIdx.x == 0) {
            float v = 0.f;
#pragma unroll
            for (int k = 0; k < GATHER_TPB / 32; k++) v += ws[k];
            out[0] = v;
        }
    }
}

// ---------------- launch ----------------
extern "C" void kernel_launch(void* const* d_in, const int* in_sizes, int n_in,
                              void* d_out, int out_size)
{
    const int*   pos_n = (const int*)d_in[0];
    const int*   pos_m = (const int*)d_in[1];
    const int*   pos_f = (const int*)d_in[2];
    const float* nci   = (const float*)d_in[3];
    const float* fmae  = (const float*)d_in[4];
    const float* Mn    = (const float*)d_in[5];
    const float* Mm    = (const float*)d_in[6];

    int B = in_sizes[0];
    int nci_rows = in_sizes[3] / DIM;
    if (nci_rows > NCI_MAX) nci_rows = NCI_MAX;
    int f_elems = in_sizes[4];
    if (f_elems > FMA_MAX * DIM) f_elems = FMA_MAX * DIM;

    int hBlocks = (nci_rows + 127) / 128;
    prep_mma<<<hBlocks + CONV_BLOCKS, 256>>>(
        nci, Mn, Mm, fmae, nci_rows, hBlocks, f_elems);
    gather_loss<<<GATHER_BLOCKS, GATHER_TPB>>>(pos_n, pos_m, pos_f, B, (float*)d_out);
}

// round 7
// speedup vs baseline: 1.1721x; 1.1721x over previous
#include <cuda_runtime.h>
#include <cuda_bf16.h>
#include <cstdint>

#define DIM 64
#define NCI_MAX 150000
#define FMA_MAX 100000
#define GATHER_BLOCKS 2048
#define GATHER_TPB 256
#define CONV_BLOCKS 512

// ---------------- scratch (device globals: allocation-free rule) ----------------
__device__ __align__(128) __nv_bfloat16 g_Hn[NCI_MAX * DIM];   // 19.2 MB
__device__ __align__(128) __nv_bfloat16 g_Hm[NCI_MAX * DIM];   // 19.2 MB
__device__ __align__(128) __nv_bfloat16 g_Fb[FMA_MAX * DIM];   // 12.8 MB
__device__ float g_part[GATHER_BLOCKS];
__device__ unsigned g_ticket;

// ---------------- HMMA: m16n8k16 bf16 -> f32 ----------------
__device__ __forceinline__ void mma16816(float* d, const uint32_t* a, const uint32_t* b) {
    asm volatile(
        "mma.sync.aligned.m16n8k16.row.col.f32.bf16.bf16.f32 "
        "{%0,%1,%2,%3}, {%4,%5,%6,%7}, {%8,%9}, {%0,%1,%2,%3};"
        : "+f"(d[0]), "+f"(d[1]), "+f"(d[2]), "+f"(d[3])
        : "r"(a[0]), "r"(a[1]), "r"(a[2]), "r"(a[3]), "r"(b[0]), "r"(b[1]));
}

#define SROW 72    // padded bf16 row stride for A/B tiles -> conflict-free fragment loads
#define OROW 136   // padded bf16 row stride for output staging -> conflict-free epilogue

// ---------------- packed f32x2 helpers ----------------
__device__ __forceinline__ unsigned long long ffma2(unsigned long long a,
                                                    unsigned long long b,
                                                    unsigned long long c) {
    unsigned long long d;
    asm("fma.rn.f32x2 %0, %1, %2, %3;" : "=l"(d) : "l"(a), "l"(b), "l"(c));
    return d;
}
__device__ __forceinline__ unsigned long long fadd2(unsigned long long a,
                                                    unsigned long long b) {
    unsigned long long d;
    asm("add.rn.f32x2 %0, %1, %2;" : "=l"(d) : "l"(a), "l"(b));
    return d;
}
__device__ __forceinline__ void unpack2(unsigned long long v, float& lo, float& hi) {
    asm("mov.b64 {%0, %1}, %2;" : "=f"(lo), "=f"(hi) : "l"(v));
}
__device__ __forceinline__ unsigned long long b2f2(unsigned u) {
    unsigned lo = u << 16;
    unsigned hi = u & 0xffff0000u;
    unsigned long long r;
    asm("mov.b64 %0, {%1, %2};" : "=l"(r) : "r"(lo), "r"(hi));
    return r;
}
__device__ __forceinline__ unsigned long long b2f2_neg(unsigned u) {
    unsigned lo = (u << 16) ^ 0x80000000u;
    unsigned hi = (u & 0xffff0000u) ^ 0x80000000u;
    unsigned long long r;
    asm("mov.b64 %0, {%1, %2};" : "=l"(r) : "r"(lo), "r"(hi));
    return r;
}

// ---------------- kernel 1: HMMA precompute + F convert (fused grid) ----------------
__global__ __launch_bounds__(256) void prep_mma(
    const float* __restrict__ nci,
    const float* __restrict__ Mn,
    const float* __restrict__ Mm,
    const float* __restrict__ fmae,
    int nrows, int hBlocks, int f_elems)
{
    const int tid = threadIdx.x;

    if (blockIdx.x >= hBlocks) {
        int cb = blockIdx.x - hBlocks;
        int stride = CONV_BLOCKS * 256;
        int nv = f_elems >> 2;
        for (int k = cb * 256 + tid; k < nv; k += stride) {
            float4 v = reinterpret_cast<const float4*>(fmae)[k];
            __nv_bfloat162* o = reinterpret_cast<__nv_bfloat162*>(g_Fb) + (size_t)k * 2;
            o[0] = __floats2bfloat162_rn(v.x, v.y);
            o[1] = __floats2bfloat162_rn(v.z, v.w);
        }
        return;
    }

    // A/B tiles and output staging alias the same shared buffer (used in phases).
    __shared__ __align__(16) __nv_bfloat16 smemBuf[2 * 128 * SROW];   // 36.9 KB
    __nv_bfloat16 (*sA)[SROW] = reinterpret_cast<__nv_bfloat16(*)[SROW]>(smemBuf);
    __nv_bfloat16 (*sB)[SROW] = reinterpret_cast<__nv_bfloat16(*)[SROW]>(smemBuf + 128 * SROW);
    __nv_bfloat16 (*sO)[OROW] = reinterpret_cast<__nv_bfloat16(*)[OROW]>(smemBuf); // 34.8 KB

    const int lane = tid & 31;
    const int w    = tid >> 5;
    const int gr   = lane >> 2;
    const int c    = lane & 3;
    const int rowBase = blockIdx.x * 128;

#pragma unroll
    for (int it = 0; it < 8; it++) {
        int idx = it * 256 + tid;
        int r = idx >> 4;
        int cq = idx & 15;
        int grow = rowBase + r;
        float4 v = (grow < nrows)
            ? reinterpret_cast<const float4*>(nci)[(size_t)grow * 16 + cq]
            : make_float4(0.f, 0.f, 0.f, 0.f);
        __nv_bfloat162 p0 = __floats2bfloat162_rn(v.x, v.y);
        __nv_bfloat162 p1 = __floats2bfloat162_rn(v.z, v.w);
        uint2 pk = make_uint2(*reinterpret_cast<uint32_t*>(&p0),
                              *reinterpret_cast<uint32_t*>(&p1));
        *reinterpret_cast<uint2*>(&sA[r][cq * 4]) = pk;
    }
#pragma unroll
    for (int it = 0; it < 8; it++) {
        int idx = it * 256 + tid;
        int r = idx >> 4;
        int cq = idx & 15;
        const float4* src = reinterpret_cast<const float4*>(r < 64 ? Mn : Mm);
        float4 v = src[(size_t)(r & 63) * 16 + cq];
        __nv_bfloat162 p0 = __floats2bfloat162_rn(v.x, v.y);
        __nv_bfloat162 p1 = __floats2bfloat162_rn(v.z, v.w);
        uint2 pk = make_uint2(*reinterpret_cast<uint32_t*>(&p0),
                              *reinterpret_cast<uint32_t*>(&p1));
        *reinterpret_cast<uint2*>(&sB[r][cq * 4]) = pk;
    }
    __syncthreads();

    float acc[16][4];
#pragma unroll
    for (int t = 0; t < 16; t++)
#pragma unroll
        for (int q = 0; q < 4; q++) acc[t][q] = 0.f;

#pragma unroll
    for (int kk = 0; kk < 4; kk++) {
        uint32_t a[4];
        const int ar0 = w * 16 + gr;
        const int ak  = kk * 16 + 2 * c;
        a[0] = *reinterpret_cast<const uint32_t*>(&sA[ar0][ak]);
        a[1] = *reinterpret_cast<const uint32_t*>(&sA[ar0 + 8][ak]);
        a[2] = *reinterpret_cast<const uint32_t*>(&sA[ar0][ak + 8]);
        a[3] = *reinterpret_cast<const uint32_t*>(&sA[ar0 + 8][ak + 8]);
#pragma unroll
        for (int t = 0; t < 16; t++) {
            uint32_t b[2];
            const int bn = t * 8 + gr;
            b[0] = *reinterpret_cast<const uint32_t*>(&sB[bn][ak]);
            b[1] = *reinterpret_cast<const uint32_t*>(&sB[bn][ak + 8]);
            mma16816(acc[t], a, b);
        }
    }

    // ---- epilogue: stage in smem, then fully coalesced STG.128 ----
    __syncthreads();   // all warps done reading sA/sB before overwrite
    {
        const int r0 = w * 16 + gr;
#pragma unroll
        for (int t = 0; t < 16; t++) {
            int col = t * 8 + 2 * c;
            __nv_bfloat162 v0 = __floats2bfloat162_rn(acc[t][0], acc[t][1]);
            __nv_bfloat162 v1 = __floats2bfloat162_rn(acc[t][2], acc[t][3]);
            *reinterpret_cast<__nv_bfloat162*>(&sO[r0][col]) = v0;
            *reinterpret_cast<__nv_bfloat162*>(&sO[r0 + 8][col]) = v1;
        }
    }
    __syncthreads();
#pragma unroll
    for (int it = 0; it < 8; it++) {
        int idx = it * 256 + tid;          // 2048 uint4 chunks total
        int half = idx >> 10;              // 0: cols 0..63 -> Hn, 1: cols 64..127 -> Hm
        int r = (idx >> 3) & 127;
        int ch = idx & 7;                  // 16B chunk within 64-col half
        int grow = rowBase + r;
        if (grow < nrows) {
            uint4 v = *reinterpret_cast<const uint4*>(&sO[r][half * 64 + ch * 8]);
            __nv_bfloat16* tab = half ? g_Hm : g_Hn;
            *reinterpret_cast<uint4*>(tab + (size_t)grow * 64 + ch * 8) = v;
        }
    }
}

// ---------------- kernel 2: 8-lane-cooperative gather + fused reduce ----------------
// (exact round-5 configuration: measured 39.7us)
__global__ __launch_bounds__(GATHER_TPB) void gather_loss(
    const int* __restrict__ pos_n,
    const int* __restrict__ pos_m,
    const int* __restrict__ pos_f,
    int B, float* __restrict__ out)
{
    const int lane = threadIdx.x & 31;
    const int wloc = threadIdx.x >> 5;
    const int warp = blockIdx.x * (GATHER_TPB >> 5) + wloc;
    const int nwarp = GATHER_BLOCKS * (GATHER_TPB >> 5);
    const int grp = lane >> 3;          // sample-group 0..3 within warp-step
    const int sub = lane & 7;           // 16B chunk within 128B row

    const char* baseHn = reinterpret_cast<const char*>(g_Hn) + sub * 16;
    const char* baseHm = reinterpret_cast<const char*>(g_Hm) + sub * 16;
    const char* baseFb = reinterpret_cast<const char*>(g_Fb) + sub * 16;

    unsigned long long accN0 = 0ull, accN1 = 0ull, accM0 = 0ull, accM1 = 0ull;

    for (int base = warp * 32; base < B; base += nwarp * 32) {
        int i = base + lane;
        int vn = 0, vm = 0, vf = 0;
        if (i < B) { vn = pos_n[i]; vm = pos_m[i]; vf = pos_f[i]; }
        const int cnt = (B - base < 32) ? (B - base) : 32;
#pragma unroll
        for (int t = 0; t < 8; t++) {
            const int s = t * 4 + grp;
            int an = __shfl_sync(0xffffffffu, vn, s);
            int am = __shfl_sync(0xffffffffu, vm, s);
            int af = __shfl_sync(0xffffffffu, vf, s);
            if (s < cnt) {
                uint4 a = *reinterpret_cast<const uint4*>(baseHn + an * 128);
                uint4 b = *reinterpret_cast<const uint4*>(baseHm + am * 128);
                uint4 f = *reinterpret_cast<const uint4*>(baseFb + af * 128);
                unsigned long long f0 = b2f2_neg(f.x);
                unsigned long long f1 = b2f2_neg(f.y);
                unsigned long long f2 = b2f2_neg(f.z);
                unsigned long long f3 = b2f2_neg(f.w);
                unsigned long long d;
                d = fadd2(b2f2(a.x), f0); accN0 = ffma2(d, d, accN0);
                d = fadd2(b2f2(a.y), f1); accN1 = ffma2(d, d, accN1);
                d = fadd2(b2f2(a.z), f2); accN0 = ffma2(d, d, accN0);
                d = fadd2(b2f2(a.w), f3); accN1 = ffma2(d, d, accN1);
                d = fadd2(b2f2(b.x), f0); accM0 = ffma2(d, d, accM0);
                d = fadd2(b2f2(b.y), f1); accM1 = ffma2(d, d, accM1);
                d = fadd2(b2f2(b.z), f2); accM0 = ffma2(d, d, accM0);
                d = fadd2(b2f2(b.w), f3); accM1 = ffma2(d, d, accM1);
            }
        }
    }

    unsigned long long accA = fadd2(accN0, accN1);
    unsigned long long accB = fadd2(accM0, accM1);
    float a0, a1, b0, b1;
    unpack2(accA, a0, a1);
    unpack2(accB, b0, b1);
    float acc = (a0 + a1) + (b0 + b1);

#pragma unroll
    for (int off = 16; off > 0; off >>= 1)
        acc += __shfl_xor_sync(0xffffffffu, acc, off);

    __shared__ float ws[GATHER_TPB / 32];
    __shared__ bool isLast;
    if (lane == 0) ws[wloc] = acc;
    __syncthreads();
    if (threadIdx.x == 0) {
        float v = 0.f;
#pragma unroll
        for (int k = 0; k < GATHER_TPB / 32; k++) v += ws[k];
        g_part[blockIdx.x] = v;
        __threadfence();
        unsigned prev = atomicInc(&g_ticket, GATHER_BLOCKS - 1);
        isLast = (prev == GATHER_BLOCKS - 1);
    }
    __syncthreads();

    if (isLast) {
        float a = 0.0f;
        for (int i = threadIdx.x; i < GATHER_BLOCKS; i += GATHER_TPB)
            a += g_part[i];
#pragma unroll
        for (int off = 16; off > 0; off >>= 1)
            a += __shfl_xor_sync(0xffffffffu, a, off);
        if (lane == 0) ws[wloc] = a;
        __syncthreads();
        if (threadIdx.x == 0) {
            float v = 0.f;
#pragma unroll
            for (int k = 0; k < GATHER_TPB / 32; k++) v += ws[k];
            out[0] = v;
        }
    }
}

// ---------------- launch ----------------
extern "C" void kernel_launch(void* const* d_in, const int* in_sizes, int n_in,
                              void* d_out, int out_size)
{
    const int*   pos_n = (const int*)d_in[0];
    const int*   pos_m = (const int*)d_in[1];
    const int*   pos_f = (const int*)d_in[2];
    const float* nci   = (const float*)d_in[3];
    const float* fmae  = (const float*)d_in[4];
    const float* Mn    = (const float*)d_in[5];
    const float* Mm    = (const float*)d_in[6];

    int B = in_sizes[0];
    int nci_rows = in_sizes[3] / DIM;
    if (nci_rows > NCI_MAX) nci_rows = NCI_MAX;
    int f_elems = in_sizes[4];
    if (f_elems > FMA_MAX * DIM) f_elems = FMA_MAX * DIM;

    int hBlocks = (nci_rows + 127) / 128;
    prep_mma<<<hBlocks + CONV_BLOCKS, 256>>>(
        nci, Mn, Mm, fmae, nci_rows, hBlocks, f_elems);
    gather_loss<<<GATHER_BLOCKS, GATHER_TPB>>>(pos_n, pos_m, pos_f, B, (float*)d_out);
}